// round 8
// baseline (speedup 1.0000x reference)
#include <cuda_runtime.h>
#include <math.h>
#include <stdint.h>

#define NN   256
#define TT   16383
#define BB   8
#define LL   2097152
#define FF   129
#define TILE 16

#define BFT ((size_t)BB * FF * TT)
#define BNT ((size_t)BB * NN * TT)
#define O_SPEC  ((size_t)0)
#define O_STFT  (BFT)
#define O_REAL  (BFT + BNT)
#define O_IMAG  (BFT + 2*BNT)
#define O_PHASE (BFT + 3*BNT)

// Replica coeff table (built on device each launch; deterministic).
__device__ float2 g_coeff[FF * NN];   // 132 KB

__device__ __forceinline__ unsigned long long pk2(float x, float y) {
    unsigned long long r;
    asm("mov.b64 %0, {%1,%2};" : "=l"(r) : "f"(x), "f"(y));
    return r;
}
__device__ __forceinline__ void upk2(unsigned long long v, float& x, float& y) {
    asm("mov.b64 {%0,%1}, %2;" : "=f"(x), "=f"(y) : "l"(v));
}
__device__ __forceinline__ void fma2(unsigned long long& d,
                                     unsigned long long a, unsigned long long b) {
    asm("fma.rn.f32x2 %0, %1, %2, %0;" : "+l"(d) : "l"(a), "l"(b));
}

// Replica of reference coeff: exp((-2i*pi/256)*(f*n)); angle = fl32(c32 * (f*n)),
// cos/sin via libdevice cosf/sinf — the SAME implementation XLA:GPU links for
// jnp.exp(complex64), so the table is bit-identical to the reference's.
__global__ void build_coeff() {
    int idx = blockIdx.x * 256 + threadIdx.x;
    if (idx >= FF * NN) return;
    int f = idx >> 8, n = idx & 255;
    const float c32 = (float)(-2.0 * M_PI / 256.0);
    float m  = (float)(f * n);               // exact integer in fp32
    float th = __fmul_rn(c32, m);            // reference's fp32 angle
    g_coeff[idx] = make_float2(cosf(th), sinf(th));
}

__global__ __launch_bounds__(256)
void dstft_main(const float* __restrict__ x,
                const float* __restrict__ wlp,
                const float* __restrict__ stp,
                const float* __restrict__ pwp,
                float* __restrict__ out)
{
    __shared__ float vt[TILE * 258];   // tapered frames; row stride 258
    __shared__ float tsum[TILE];
    __shared__ float sfrac[TILE];
    __shared__ int   sidx0[TILE];
    __shared__ float mcs[TILE], msn[TILE];

    const int tid = threadIdx.x;
    const int b   = blockIdx.y;
    const int t0  = blockIdx.x * TILE;

    const float wl = fminf(fmaxf(wlp[0], 12.8f), 256.0f);
    const float st = fminf(fmaxf(stp[0], 0.0f), 256.0f);
    const float p  = pwp[0];

    if (tid < TILE) {
        int t = t0 + tid;
        float fv = __fmul_rn((float)t, st);   // == fp32 cumsum (exact here)
        float fl = floorf(fv);
        float fc = __fsub_rn(fv, fl);
        sfrac[tid] = fc;
        sidx0[tid] = (int)fl;
        // mirror rotation e^{2*pi*i*frac} (feeds outputs 1-3 only; loose tol)
        float thm = __fmul_rn((float)(2.0 * M_PI / 256.0),
                              __fmul_rn(fc, 256.0f));
        mcs[tid] = cosf(thm);
        msn[tid] = sinf(thm);
    }
    __syncthreads();

    // ---- A1: hann taps (replica fp32 ops; cosf = libdevice, same as jnp.cos) ----
    const float hi  = ceilf (__fdiv_rn(__fadd_rn(255.0f, wl), 2.0f));
    const float lo  = floorf(__fdiv_rn(__fsub_rn(255.0f, wl), 2.0f));
    const float off = __fdiv_rn(__fadd_rn(__fsub_rn(wl, 256.0f), 1.0f), 2.0f);
    const float twopi = (float)(2.0 * M_PI);
    #pragma unroll
    for (int k = 0; k < TILE; ++k) {
        float base = __fsub_rn((float)tid, sfrac[k]);
        float arg  = __fdiv_rn(__fmul_rn(twopi, __fadd_rn(base, off)), wl);
        float tap  = __fsub_rn(0.5f, __fmul_rn(0.5f, cosf(arg)));
        if (base >= hi) tap = 0.0f;
        if (base <= lo) tap = 0.0f;
        vt[k * 258 + tid] = tap;
    }
    __syncthreads();

    // ---- A2: per-frame tap sums ----
    {
        int w = tid >> 5, lane = tid & 31;
        for (int k0 = 0; k0 < TILE; k0 += 8) {
            int k = k0 + w;
            float s = 0.0f;
            #pragma unroll
            for (int j = 0; j < 256; j += 32) s += vt[k * 258 + j + lane];
            #pragma unroll
            for (int o = 16; o > 0; o >>= 1) s += __shfl_down_sync(0xffffffffu, s, o);
            if (lane == 0) tsum[k] = s;
        }
    }
    __syncthreads();

    // ---- A3: tapered = x_gather * (tap / sum) [^p] ----
    {
        const float* xb = x + (size_t)b * LL;
        #pragma unroll
        for (int k = 0; k < TILE; ++k) {
            int t = t0 + k;
            float v = 0.0f;
            if (t < TT) {
                int gi = sidx0[k] + tid;
                float xv = (gi >= 0 && gi < LL) ? xb[gi] : 0.0f;
                float tapn = __fdiv_rn(vt[k * 258 + tid], tsum[k]);
                if (p != 1.0f) tapn = powf(tapn, p);
                v = __fmul_rn(xv, tapn);
            }
            vt[k * 258 + tid] = v;
        }
    }
    __syncthreads();

    // ---- B: direct DFT, sequential-n fp32 FMA accumulation (cgemm-order) ----
    const int fr    = tid & 15;
    const int fslot = tid >> 4;

    unsigned long long acc[9];
    #pragma unroll
    for (int i = 0; i < 9; ++i) acc[i] = 0ull;

    const ulonglong2* rp[9];
    #pragma unroll
    for (int i = 0; i < 9; ++i) {
        int f = fslot + 16 * i;
        if (f > 128) f = 128;                 // i==8 only valid for fslot==0
        rp[i] = (const ulonglong2*)(g_coeff + f * 256);
    }

    #pragma unroll 4
    for (int n = 0; n < 256; n += 2) {
        float2 vv = *(const float2*)&vt[fr * 258 + n];
        unsigned long long a0 = pk2(vv.x, vv.x);
        unsigned long long a1 = pk2(vv.y, vv.y);
        #pragma unroll
        for (int i = 0; i < 9; ++i) {
            ulonglong2 c = __ldg(rp[i] + (n >> 1));
            fma2(acc[i], a0, c.x);
            fma2(acc[i], a1, c.y);
        }
    }

    // ---- C: sub-sample shift + outputs ----
    const int t = t0 + fr;
    if (t < TT) {
        const float c2 = (float)(2.0 * M_PI / 256.0);
        const float frac = sfrac[fr];
        #pragma unroll
        for (int i = 0; i < 9; ++i) {
            int f = fslot + 16 * i;
            if (f > 128) continue;
            float Xr, Xi;
            upk2(acc[i], Xr, Xi);
            // replica shift: angle = fl32(c2 * fl32(frac*f)); libdevice sincos
            float th = __fmul_rn(c2, __fmul_rn(frac, (float)f));
            float shc = cosf(th), shs = sinf(th);
            // replica complex multiply (uncontracted mul/mul/sub|add)
            float Xr2 = __fsub_rn(__fmul_rn(Xr, shc), __fmul_rn(Xi, shs));
            float Xi2 = __fadd_rn(__fmul_rn(Xr, shs), __fmul_rn(Xi, shc));

            float spec = sqrtf(__fmaf_rn(Xr2, Xr2, __fmul_rn(Xi2, Xi2))) + 1.1920929e-7f;
            float ph   = atan2f(Xi2, Xr2);

            size_t ibf = ((size_t)b * FF + f) * TT + t;
            size_t ib  = ((size_t)b * NN + f) * TT + t;
            out[O_SPEC  + ibf] = spec;
            out[O_PHASE + ibf] = ph;
            out[O_STFT  + ib ] = Xr2;
            out[O_REAL  + ib ] = Xr2;
            out[O_IMAG  + ib ] = Xi2;

            if (f >= 1 && f <= 127) {
                float cp = mcs[fr], sp = msn[fr];
                float Xr3 = cp * Xr2 + sp * Xi2;   // e^{2pi i frac} * conj(X)
                float Xi3 = sp * Xr2 - cp * Xi2;
                size_t ib2 = ((size_t)b * NN + (NN - f)) * TT + t;
                out[O_STFT + ib2] = Xr3;
                out[O_REAL + ib2] = Xr3;
                out[O_IMAG + ib2] = Xi3;
            }
        }
    }
}

extern "C" void kernel_launch(void* const* d_in, const int* in_sizes, int n_in,
                              void* d_out, int out_size) {
    // Confirmed (R5 diagnostics): in_sizes in elements, insertion order:
    // x(16777216), win_length(1), strides(1), win_pow(1).
    // out_size = 134,471,664 float32 elements: spec|stft.re|real|imag|phase.
    const float* x  = (const float*)d_in[0];
    const float* wl = (const float*)d_in[1];
    const float* st = (const float*)d_in[2];
    const float* pw = (const float*)d_in[3];
    float* out = (float*)d_out;

    build_coeff<<<(FF * NN + 255) / 256, 256>>>();

    dim3 grid((TT + TILE - 1) / TILE, BB);
    dstft_main<<<grid, 256>>>(x, wl, st, pw, out);
}

// round 9
// speedup vs baseline: 1.4305x; 1.4305x over previous
#include <cuda_runtime.h>
#include <math.h>
#include <stdint.h>

#define NN   256
#define TT   16383
#define BB   8
#define LL   2097152
#define FF   129
#define TILE 64            // frames per block
#define NBLK ((TT + TILE - 1) / TILE)   // 256

#define BFT ((size_t)BB * FF * TT)
#define BNT ((size_t)BB * NN * TT)
#define O_SPEC  ((size_t)0)
#define O_STFT  (BFT)
#define O_REAL  (BFT + BNT)
#define O_IMAG  (BFT + 2*BNT)
#define O_PHASE (BFT + 3*BNT)

// Replica coeff table padded to 144 rows (f=129..143 are dummy, read-safe).
#define CROWS 144
__device__ float2 g_coeff[CROWS * NN];   // 294 KB

__device__ __forceinline__ unsigned long long pk2(float x, float y) {
    unsigned long long r;
    asm("mov.b64 %0, {%1,%2};" : "=l"(r) : "f"(x), "f"(y));
    return r;
}
__device__ __forceinline__ void upk2(unsigned long long v, float& x, float& y) {
    asm("mov.b64 {%0,%1}, %2;" : "=f"(x), "=f"(y) : "l"(v));
}
__device__ __forceinline__ void fma2(unsigned long long& d,
                                     unsigned long long a, unsigned long long b) {
    asm("fma.rn.f32x2 %0, %1, %2, %0;" : "+l"(d) : "l"(a), "l"(b));
}

// Replica of reference coeff: exp((-2i*pi/256)*(f*n)); angle = fl32(c32*(f*n)),
// cos/sin via libdevice cosf/sinf (bit-identical to XLA:GPU's jnp.exp lowering).
__global__ void build_coeff() {
    int idx = blockIdx.x * 256 + threadIdx.x;
    if (idx >= CROWS * NN) return;
    int f = idx >> 8, n = idx & 255;
    const float c32 = (float)(-2.0 * M_PI / 256.0);
    float m  = (float)(f * n);               // exact integer in fp32
    float th = __fmul_rn(c32, m);
    g_coeff[idx] = make_float2(cosf(th), sinf(th));
}

__global__ __launch_bounds__(256, 2)
void dstft_main(const float* __restrict__ x,
                const float* __restrict__ wlp,
                const float* __restrict__ stp,
                const float* __restrict__ pwp,
                float* __restrict__ out)
{
    extern __shared__ float smem[];
    float* vt    = smem;                       // [TILE][258]
    float* tsum  = smem + TILE * 258;          // [TILE]
    float* sfrac = tsum + TILE;                // [TILE]
    float* mcs   = sfrac + TILE;               // [TILE]
    float* msn   = mcs + TILE;                 // [TILE]
    int*   sidx0 = (int*)(msn + TILE);         // [TILE]

    const int tid = threadIdx.x;
    const int b   = blockIdx.y;
    const int t0  = blockIdx.x * TILE;

    const float wl = fminf(fmaxf(wlp[0], 12.8f), 256.0f);
    const float st = fminf(fmaxf(stp[0], 0.0f), 256.0f);
    const float p  = pwp[0];

    if (tid < TILE) {
        int t = t0 + tid;
        float fv = __fmul_rn((float)t, st);   // == fp32 cumsum (exact here)
        float fl = floorf(fv);
        float fc = __fsub_rn(fv, fl);
        sfrac[tid] = fc;
        sidx0[tid] = (int)fl;
        float thm = __fmul_rn((float)(2.0 * M_PI / 256.0),
                              __fmul_rn(fc, 256.0f));
        mcs[tid] = cosf(thm);
        msn[tid] = sinf(thm);
    }
    __syncthreads();

    // ---- A1: hann taps (replica fp32 ops) ----
    const float hi  = ceilf (__fdiv_rn(__fadd_rn(255.0f, wl), 2.0f));
    const float lo  = floorf(__fdiv_rn(__fsub_rn(255.0f, wl), 2.0f));
    const float off = __fdiv_rn(__fadd_rn(__fsub_rn(wl, 256.0f), 1.0f), 2.0f);
    const float twopi = (float)(2.0 * M_PI);
    for (int k = 0; k < TILE; ++k) {
        float base = __fsub_rn((float)tid, sfrac[k]);
        float arg  = __fdiv_rn(__fmul_rn(twopi, __fadd_rn(base, off)), wl);
        float tap  = __fsub_rn(0.5f, __fmul_rn(0.5f, cosf(arg)));
        if (base >= hi) tap = 0.0f;
        if (base <= lo) tap = 0.0f;
        vt[k * 258 + tid] = tap;
    }
    __syncthreads();

    // ---- A2: per-frame tap sums (same reduction order as R8) ----
    {
        int w = tid >> 5, lane = tid & 31;
        for (int k0 = 0; k0 < TILE; k0 += 8) {
            int k = k0 + w;
            float s = 0.0f;
            #pragma unroll
            for (int j = 0; j < 256; j += 32) s += vt[k * 258 + j + lane];
            #pragma unroll
            for (int o = 16; o > 0; o >>= 1) s += __shfl_down_sync(0xffffffffu, s, o);
            if (lane == 0) tsum[k] = s;
        }
    }
    __syncthreads();

    // ---- A3: tapered = x_gather * (tap / sum) [^p] ----
    {
        const float* xb = x + (size_t)b * LL;
        for (int k = 0; k < TILE; ++k) {
            int t = t0 + k;
            float v = 0.0f;
            if (t < TT) {
                int gi = sidx0[k] + tid;
                float xv = (gi >= 0 && gi < LL) ? xb[gi] : 0.0f;
                float tapn = __fdiv_rn(vt[k * 258 + tid], tsum[k]);
                if (p != 1.0f) tapn = powf(tapn, p);
                v = __fmul_rn(xv, tapn);
            }
            vt[k * 258 + tid] = v;
        }
    }
    __syncthreads();

    // ---- B: direct DFT; each thread: 9 f-slots x 4 frames ----
    const int fr    = tid & 15;     // frame-group: frames fr + 16j
    const int fslot = tid >> 4;     // f = fslot + 16i

    unsigned long long acc[36];
    #pragma unroll
    for (int i = 0; i < 36; ++i) acc[i] = 0ull;

    const char* cbase = (const char*)(g_coeff + fslot * 256);

    #pragma unroll 2
    for (int n = 0; n < 256; n += 2) {
        unsigned long long a0[4], a1[4];
        #pragma unroll
        for (int j = 0; j < 4; ++j) {
            float2 vv = *(const float2*)&vt[(fr + 16 * j) * 258 + n];
            a0[j] = pk2(vv.x, vv.x);
            a1[j] = pk2(vv.y, vv.y);
        }
        const char* cp = cbase + n * 8;
        #pragma unroll
        for (int i = 0; i < 9; ++i) {
            ulonglong2 c = __ldg((const ulonglong2*)(cp + i * 32768));
            #pragma unroll
            for (int j = 0; j < 4; ++j) {
                fma2(acc[i * 4 + j], a0[j], c.x);
                fma2(acc[i * 4 + j], a1[j], c.y);
            }
        }
    }

    // ---- C: sub-sample shift + outputs ----
    const float c2 = (float)(2.0 * M_PI / 256.0);
    #pragma unroll
    for (int i = 0; i < 9; ++i) {
        int f = fslot + 16 * i;
        if (f > 128) continue;
        #pragma unroll
        for (int j = 0; j < 4; ++j) {
            int frame = fr + 16 * j;
            int t = t0 + frame;
            if (t >= TT) continue;
            float Xr, Xi;
            upk2(acc[i * 4 + j], Xr, Xi);

            float frac = sfrac[frame];
            float th = __fmul_rn(c2, __fmul_rn(frac, (float)f));
            float shc = cosf(th), shs = sinf(th);
            float Xr2 = __fsub_rn(__fmul_rn(Xr, shc), __fmul_rn(Xi, shs));
            float Xi2 = __fadd_rn(__fmul_rn(Xr, shs), __fmul_rn(Xi, shc));

            float spec = sqrtf(__fmaf_rn(Xr2, Xr2, __fmul_rn(Xi2, Xi2))) + 1.1920929e-7f;
            float ph   = atan2f(Xi2, Xr2);

            size_t ibf = ((size_t)b * FF + f) * TT + t;
            size_t ib  = ((size_t)b * NN + f) * TT + t;
            out[O_SPEC  + ibf] = spec;
            out[O_PHASE + ibf] = ph;
            out[O_STFT  + ib ] = Xr2;
            out[O_REAL  + ib ] = Xr2;
            out[O_IMAG  + ib ] = Xi2;

            if (f >= 1 && f <= 127) {
                float cp2 = mcs[frame], sp2 = msn[frame];
                float Xr3 = cp2 * Xr2 + sp2 * Xi2;   // e^{2pi i frac} * conj(X)
                float Xi3 = sp2 * Xr2 - cp2 * Xi2;
                size_t ib2 = ((size_t)b * NN + (NN - f)) * TT + t;
                out[O_STFT + ib2] = Xr3;
                out[O_REAL + ib2] = Xr3;
                out[O_IMAG + ib2] = Xi3;
            }
        }
    }
}

extern "C" void kernel_launch(void* const* d_in, const int* in_sizes, int n_in,
                              void* d_out, int out_size) {
    const float* x  = (const float*)d_in[0];
    const float* wl = (const float*)d_in[1];
    const float* st = (const float*)d_in[2];
    const float* pw = (const float*)d_in[3];
    float* out = (float*)d_out;

    build_coeff<<<(CROWS * NN + 255) / 256, 256>>>();

    const int smemBytes = (TILE * 258 + TILE * 5) * 4;   // ~67.3 KB
    static int attrSet = 0;
    if (!attrSet) {
        cudaFuncSetAttribute(dstft_main,
                             cudaFuncAttributeMaxDynamicSharedMemorySize,
                             smemBytes);
        attrSet = 1;
    }

    dim3 grid(NBLK, BB);
    dstft_main<<<grid, 256, smemBytes>>>(x, wl, st, pw, out);
}